// round 15
// baseline (speedup 1.0000x reference)
#include <cuda_runtime.h>
#include <math.h>

#define BATCH  64
#define HID    512
#define EMBD   200
#define VOCAB  32000
#define SRCLEN 64
#define TGTLEN 64
#define NBLK   296
#define NTHR   256
#define SB     (BATCH*HID)
#define PARTSZ (BATCH*2048)
#define NSPL   8
#define FCT    250   /* 32000/128 */

typedef unsigned long long ull;

__device__ __forceinline__ ull pack2(float a, float b) {
    ull r; asm("mov.b64 %0, {%1,%2};" : "=l"(r) : "f"(a), "f"(b)); return r;
}
__device__ __forceinline__ ull ffma2(ull a, ull b, ull c) {
    ull d; asm("fma.rn.f32x2 %0, %1, %2, %3;" : "=l"(d) : "l"(a), "l"(b), "l"(c)); return d;
}
__device__ __forceinline__ float2 unpk(ull v) {
    float2 r; asm("mov.b64 {%0,%1}, %2;" : "=f"(r.x), "=f"(r.y) : "l"(v)); return r;
}

__device__ __align__(16) float g_parts0[NSPL*PARTSZ];
__device__ __align__(16) float g_parts1[NSPL*PARTSZ];
__device__ __align__(16) float g_h0[SB], g_c0[SB], g_h1[SB], g_c1[SB];
__device__ __align__(16) float g_bsum[4*2048];
__device__ int g_xtok[BATCH];
__device__ __align__(16) float g_pval[256*BATCH];
__device__ int g_pidx[256*BATCH];
__device__ unsigned g_barcnt;
__device__ volatile unsigned g_bargen;

__device__ __forceinline__ void gridbar() {
    __syncthreads();
    if (threadIdx.x == 0) {
        __threadfence();
        unsigned gen = g_bargen;
        if (atomicAdd(&g_barcnt, 1u) == NBLK - 1u) {
            g_barcnt = 0u;
            __threadfence();
            g_bargen = gen + 1u;
        } else {
            while (g_bargen == gen) __nanosleep(64);
            __threadfence();
        }
    }
    __syncthreads();
}

// ---- 64-col tile: acc[4b][2] += X[rows][k]*W[c][k], X staged as dup pairs ----
__device__ __forceinline__ void tile64(
    const float* __restrict__ W, int ldW,
    const float* __restrict__ X, int ldX,
    const int* rows, int kbeg, int kend,
    float* Ws, ull* Xs, ull acc[4][2])
{
    int tid = threadIdx.x;
    int sj = tid >> 2, sk = (tid & 3) << 2;
    int rg = (tid >> 4) << 2, cg = (tid & 15) << 2;
    const float* Wp = W + (size_t)sj*ldW;
    const float* Xp = X + (size_t)rows[sj]*ldX;
    int nch = (kend - kbeg + 15) >> 4;
    float4 wv, xv;
    int kg = kbeg + sk;
    if (kg + 4 <= kend) { wv = *(const float4*)&Wp[kg]; xv = __ldcg((const float4*)&Xp[kg]); }
    else wv = xv = make_float4(0.f,0.f,0.f,0.f);
    {
        float* w_ = Ws + sk*68 + sj; ull* x_ = Xs + sk*66 + sj;
        w_[0]=wv.x; w_[68]=wv.y; w_[136]=wv.z; w_[204]=wv.w;
        x_[0]=pack2(xv.x,xv.x); x_[66]=pack2(xv.y,xv.y);
        x_[132]=pack2(xv.z,xv.z); x_[198]=pack2(xv.w,xv.w);
    }
    __syncthreads();
    if (nch > 1) {
        kg = kbeg + 16 + sk;
        if (kg + 4 <= kend) { wv = *(const float4*)&Wp[kg]; xv = __ldcg((const float4*)&Xp[kg]); }
        else wv = xv = make_float4(0.f,0.f,0.f,0.f);
    }
    for (int c = 0; c < nch; ++c) {
        int cb = c & 1;
        if (c + 1 < nch) {
            float* w_ = Ws + (cb^1)*1088 + sk*68 + sj;
            ull*   x_ = Xs + (cb^1)*1056 + sk*66 + sj;
            w_[0]=wv.x; w_[68]=wv.y; w_[136]=wv.z; w_[204]=wv.w;
            x_[0]=pack2(xv.x,xv.x); x_[66]=pack2(xv.y,xv.y);
            x_[132]=pack2(xv.z,xv.z); x_[198]=pack2(xv.w,xv.w);
        }
        if (c + 2 < nch) {
            kg = kbeg + (c+2)*16 + sk;
            if (kg + 4 <= kend) { wv = *(const float4*)&Wp[kg]; xv = __ldcg((const float4*)&Xp[kg]); }
            else wv = xv = make_float4(0.f,0.f,0.f,0.f);
        }
        const float* Wb = Ws + cb*1088;
        const ull*   Xb = Xs + cb*1056;
        #pragma unroll
        for (int q = 0; q < 16; ++q) {
            ulonglong2 xa = *(const ulonglong2*)&Xb[q*66 + rg];
            ulonglong2 xb = *(const ulonglong2*)&Xb[q*66 + rg + 2];
            ulonglong2 w2 = *(const ulonglong2*)&Wb[q*68 + cg];
            acc[0][0]=ffma2(xa.x,w2.x,acc[0][0]); acc[0][1]=ffma2(xa.x,w2.y,acc[0][1]);
            acc[1][0]=ffma2(xa.y,w2.x,acc[1][0]); acc[1][1]=ffma2(xa.y,w2.y,acc[1][1]);
            acc[2][0]=ffma2(xb.x,w2.x,acc[2][0]); acc[2][1]=ffma2(xb.x,w2.y,acc[2][1]);
            acc[3][0]=ffma2(xb.y,w2.x,acc[3][0]); acc[3][1]=ffma2(xb.y,w2.y,acc[3][1]);
        }
        __syncthreads();
    }
}

// ---- 128-col FC tile: acc[4b][4] (8 cols/thread), K=512 ----
__device__ __forceinline__ void tile128(
    const float* __restrict__ W, const float* __restrict__ X,
    float* Ws, ull* Xs, ull acc[4][4])
{
    int tid = threadIdx.x;
    int wj = tid >> 1, wk = (tid & 1) << 3;
    int xj = tid >> 2, xk = (tid & 3) << 2;
    int rg = (tid >> 4) << 2, cg = (tid & 15) << 3;
    const float* Wp = W + (size_t)wj*HID;
    const float* Xp = X + (size_t)xj*HID;
    const int nch = HID/16;
    float4 wa, wb, xv;
    wa = *(const float4*)&Wp[wk]; wb = *(const float4*)&Wp[wk+4];
    xv = __ldcg((const float4*)&Xp[xk]);
    {
        float* w_ = Ws + wk*132 + wj; ull* x_ = Xs + xk*66 + xj;
        w_[0]=wa.x; w_[132]=wa.y; w_[264]=wa.z; w_[396]=wa.w;
        w_[528]=wb.x; w_[660]=wb.y; w_[792]=wb.z; w_[924]=wb.w;
        x_[0]=pack2(xv.x,xv.x); x_[66]=pack2(xv.y,xv.y);
        x_[132]=pack2(xv.z,xv.z); x_[198]=pack2(xv.w,xv.w);
    }
    __syncthreads();
    wa = *(const float4*)&Wp[16+wk]; wb = *(const float4*)&Wp[16+wk+4];
    xv = __ldcg((const float4*)&Xp[16+xk]);
    for (int c = 0; c < nch; ++c) {
        int cb = c & 1;
        if (c + 1 < nch) {
            float* w_ = Ws + (cb^1)*2112 + wk*132 + wj;
            ull*   x_ = Xs + (cb^1)*1056 + xk*66 + xj;
            w_[0]=wa.x; w_[132]=wa.y; w_[264]=wa.z; w_[396]=wa.w;
            w_[528]=wb.x; w_[660]=wb.y; w_[792]=wb.z; w_[924]=wb.w;
            x_[0]=pack2(xv.x,xv.x); x_[66]=pack2(xv.y,xv.y);
            x_[132]=pack2(xv.z,xv.z); x_[198]=pack2(xv.w,xv.w);
        }
        if (c + 2 < nch) {
            int k0 = (c+2)*16;
            wa = *(const float4*)&Wp[k0+wk]; wb = *(const float4*)&Wp[k0+wk+4];
            xv = __ldcg((const float4*)&Xp[k0+xk]);
        }
        const float* Wb = Ws + cb*2112;
        const ull*   Xb = Xs + cb*1056;
        #pragma unroll
        for (int q = 0; q < 16; ++q) {
            ulonglong2 xa = *(const ulonglong2*)&Xb[q*66 + rg];
            ulonglong2 xb = *(const ulonglong2*)&Xb[q*66 + rg + 2];
            ulonglong2 w0 = *(const ulonglong2*)&Wb[q*132 + cg];
            ulonglong2 w1 = *(const ulonglong2*)&Wb[q*132 + cg + 4];
            acc[0][0]=ffma2(xa.x,w0.x,acc[0][0]); acc[0][1]=ffma2(xa.x,w0.y,acc[0][1]);
            acc[0][2]=ffma2(xa.x,w1.x,acc[0][2]); acc[0][3]=ffma2(xa.x,w1.y,acc[0][3]);
            acc[1][0]=ffma2(xa.y,w0.x,acc[1][0]); acc[1][1]=ffma2(xa.y,w0.y,acc[1][1]);
            acc[1][2]=ffma2(xa.y,w1.x,acc[1][2]); acc[1][3]=ffma2(xa.y,w1.y,acc[1][3]);
            acc[2][0]=ffma2(xb.x,w0.x,acc[2][0]); acc[2][1]=ffma2(xb.x,w0.y,acc[2][1]);
            acc[2][2]=ffma2(xb.x,w1.x,acc[2][2]); acc[2][3]=ffma2(xb.x,w1.y,acc[2][3]);
            acc[3][0]=ffma2(xb.y,w0.x,acc[3][0]); acc[3][1]=ffma2(xb.y,w0.y,acc[3][1]);
            acc[3][2]=ffma2(xb.y,w1.x,acc[3][2]); acc[3][3]=ffma2(xb.y,w1.y,acc[3][3]);
        }
        __syncthreads();
    }
}

__device__ __forceinline__ void split_range(int layer, int ks, int& isih, int& kbeg, int& kend) {
    if (layer == 0) {
        if (ks < 2) { isih = 1; kbeg = ks ? 112 : 0; kend = ks ? 200 : 112; }
        else {
            isih = 0;
            int h = ks - 2;
            kbeg = (h < 2) ? h*88 : 176 + (h-2)*84;
            kend = (h < 2) ? kbeg + 88 : kbeg + 84;
        }
    } else {
        isih = (ks < 4);
        kbeg = (ks & 3)*128; kend = kbeg + 128;
    }
}

__device__ __forceinline__ void gates_job(
    int job, int layer,
    const float* __restrict__ Wih, const float* __restrict__ Whh,
    const float* __restrict__ xsrc, const int* __restrict__ toks,
    const float* __restrict__ hprev, float* __restrict__ parts,
    float* Ws, ull* Xs, int* s_rows)
{
    int ks = job >> 5, ti = job & 31, tid = threadIdx.x;
    int isih, kbeg, kend;
    split_range(layer, ks, isih, kbeg, kend);
    const float *W, *X; int ldW, ldX, gather;
    if (isih) {
        ldW = (layer == 0) ? EMBD : HID;
        W = Wih; X = xsrc; ldX = ldW;
        gather = (layer == 0);
    } else {
        W = Whh; ldW = HID; X = hprev; ldX = HID; gather = 0;
    }
    __syncthreads();
    if (tid < 64) s_rows[tid] = gather ? __ldcg(&toks[tid]) : tid;
    __syncthreads();
    ull acc[4][2] = {{0,0},{0,0},{0,0},{0,0}};
    tile64(W + (size_t)(ti*64)*ldW, ldW, X, ldX, s_rows, kbeg, kend, Ws, Xs, acc);
    int rg = tid >> 4, cg = tid & 15;
    #pragma unroll
    for (int r = 0; r < 4; ++r) {
        float2 a = unpk(acc[r][0]), b = unpk(acc[r][1]);
        *(float4*)&parts[(size_t)ks*PARTSZ + (size_t)(rg*4+r)*2048 + ti*64 + cg*4] =
            make_float4(a.x, a.y, b.x, b.y);
    }
}

__device__ __forceinline__ void epi_elem(int e, const float* __restrict__ bsum,
                                         const float* __restrict__ parts,
                                         float* __restrict__ h, float* __restrict__ c)
{
    int b = e >> 9, j = e & 511;
    float s[4];
    #pragma unroll
    for (int g = 0; g < 4; ++g) {
        int col = (g << 9) + j;
        float v = bsum[col];
        #pragma unroll
        for (int ks = 0; ks < NSPL; ++ks)
            v += __ldcg(&parts[(size_t)ks*PARTSZ + (size_t)b*2048 + col]);
        s[g] = v;
    }
    float iv = 1.f/(1.f+expf(-s[0])), fv = 1.f/(1.f+expf(-s[1]));
    float gv = tanhf(s[2]),           ov = 1.f/(1.f+expf(-s[3]));
    float cn = fv*__ldcg(&c[e]) + iv*gv;
    c[e] = cn;
    h[e] = ov*tanhf(cn);
}

__device__ __forceinline__ void fc_job(
    int vt, const float* __restrict__ fcW, const float* __restrict__ fcb,
    float* __restrict__ out, float* Ws, ull* Xs,
    float* s_red, int* s_redi)
{
    int tid = threadIdx.x;
    __syncthreads();
    ull acc[4][4] = {{0,0,0,0},{0,0,0,0},{0,0,0,0},{0,0,0,0}};
    tile128(fcW + (size_t)(vt*128)*HID, g_h1, Ws, Xs, acc);
    int rg = tid >> 4, cg = tid & 15, c0 = vt*128 + cg*8;
    float4 bva = *(const float4*)&fcb[c0];
    float4 bvb = *(const float4*)&fcb[c0+4];
    #pragma unroll
    for (int r = 0; r < 4; ++r) {
        int b = rg*4 + r;
        float2 p0 = unpk(acc[r][0]), p1 = unpk(acc[r][1]);
        float2 p2 = unpk(acc[r][2]), p3 = unpk(acc[r][3]);
        float v[8];
        v[0]=p0.x+bva.x; v[1]=p0.y+bva.y; v[2]=p1.x+bva.z; v[3]=p1.y+bva.w;
        v[4]=p2.x+bvb.x; v[5]=p2.y+bvb.y; v[6]=p3.x+bvb.z; v[7]=p3.y+bvb.w;
        float* p = out + (size_t)b*VOCAB + c0;
        *(float4*)p     = make_float4(v[0],v[1],v[2],v[3]);
        *(float4*)(p+4) = make_float4(v[4],v[5],v[6],v[7]);
        float best = v[0]; int bi = 0;
        #pragma unroll
        for (int u = 1; u < 8; ++u)
            if (v[u] > best) { best = v[u]; bi = u; }
        s_red[b*16 + cg] = best; s_redi[b*16 + cg] = c0 + bi;
    }
    __syncthreads();
    if (tid < 64) {
        float best = s_red[tid*16]; int bi = s_redi[tid*16];
        #pragma unroll
        for (int u = 1; u < 16; ++u) {
            float v = s_red[tid*16 + u];
            if (v > best) { best = v; bi = s_redi[tid*16 + u]; }
        }
        g_pval[vt*BATCH + tid] = best;
        g_pidx[vt*BATCH + tid] = bi;
    }
}

__global__ void __launch_bounds__(NTHR, 2) seq2seq_all(
    const float* __restrict__ enc_embed,
    const float* __restrict__ eWih0, const float* __restrict__ eWhh0,
    const float* __restrict__ ebih0, const float* __restrict__ ebhh0,
    const float* __restrict__ eWih1, const float* __restrict__ eWhh1,
    const float* __restrict__ ebih1, const float* __restrict__ ebhh1,
    const float* __restrict__ dec_embed,
    const float* __restrict__ dWih0, const float* __restrict__ dWhh0,
    const float* __restrict__ dbih0, const float* __restrict__ dbhh0,
    const float* __restrict__ dWih1, const float* __restrict__ dWhh1,
    const float* __restrict__ dbih1, const float* __restrict__ dbhh1,
    const float* __restrict__ fcW, const float* __restrict__ fcb,
    const int* __restrict__ src, const int* __restrict__ target,
    const int* __restrict__ tfmask, float* __restrict__ out)
{
    __shared__ __align__(16) float Ws[2*2112];
    __shared__ __align__(16) ull   Xs[2*1056];
    __shared__ int   s_rows[64];
    __shared__ float s_red[1024];
    __shared__ int   s_redi[1024];

    int bid = blockIdx.x, tid = threadIdx.x;
    int gtid = bid*NTHR + tid;
    const int GSTR = NBLK*NTHR;

    for (int e = gtid; e < SB; e += GSTR) { g_h0[e]=0.f; g_c0[e]=0.f; g_h1[e]=0.f; g_c1[e]=0.f; }
    for (int e = gtid; e < 2048; e += GSTR) {
        g_bsum[e]      = ebih0[e] + ebhh0[e];
        g_bsum[2048+e] = ebih1[e] + ebhh1[e];
        g_bsum[4096+e] = dbih0[e] + dbhh0[e];
        g_bsum[6144+e] = dbih1[e] + dbhh1[e];
    }
    if (gtid < BATCH) g_xtok[gtid] = target[gtid];
    gridbar();

    // ---- encoder ----
    for (int job = bid; job < 256; job += NBLK)
        gates_job(job, 0, eWih0, eWhh0, enc_embed, src, g_h0, g_parts0, Ws, Xs, s_rows);
    gridbar();
    for (int e = gtid; e < SB; e += GSTR) epi_elem(e, g_bsum, g_parts0, g_h0, g_c0);
    gridbar();
    for (int s = 0; s < SRCLEN-1; ++s) {
        for (int job = bid; job < 512; job += NBLK) {
            if (job < 256)
                gates_job(job, 1, eWih1, eWhh1, g_h0, (const int*)0, g_h1, g_parts1, Ws, Xs, s_rows);
            else
                gates_job(job-256, 0, eWih0, eWhh0, enc_embed, src + (s+1)*BATCH, g_h0, g_parts0, Ws, Xs, s_rows);
        }
        gridbar();
        for (int e = gtid; e < 2*SB; e += GSTR) {
            if (e < SB) epi_elem(e,    g_bsum+2048, g_parts1, g_h1, g_c1);
            else        epi_elem(e-SB, g_bsum,      g_parts0, g_h0, g_c0);
        }
        gridbar();
    }
    for (int job = bid; job < 256; job += NBLK)
        gates_job(job, 1, eWih1, eWhh1, g_h0, (const int*)0, g_h1, g_parts1, Ws, Xs, s_rows);
    gridbar();
    for (int e = gtid; e < SB; e += GSTR) epi_elem(e, g_bsum+2048, g_parts1, g_h1, g_c1);
    gridbar();

    // ---- decoder ----
    for (int t = 1; t < TGTLEN; ++t) {
        for (int job = bid; job < 256; job += NBLK)
            gates_job(job, 0, dWih0, dWhh0, dec_embed, g_xtok, g_h0, g_parts0, Ws, Xs, s_rows);
        gridbar();
        for (int e = gtid; e < SB; e += GSTR) epi_elem(e, g_bsum+4096, g_parts0, g_h0, g_c0);
        gridbar();
        for (int job = bid; job < 256; job += NBLK)
            gates_job(job, 1, dWih1, dWhh1, g_h0, (const int*)0, g_h1, g_parts1, Ws, Xs, s_rows);
        gridbar();
        for (int e = gtid; e < SB; e += GSTR) epi_elem(e, g_bsum+6144, g_parts1, g_h1, g_c1);
        gridbar();

        float* outT = out + (size_t)t*BATCH*VOCAB;
        for (int vt = bid; vt < FCT; vt += NBLK)
            fc_job(vt, fcW, fcb, outT, Ws, Xs, s_red, s_redi);
        gridbar();

        if (bid < BATCH) {
            int b = bid;
            float best = -3.4e38f; int bi = 0;
            if (tid < FCT) {
                best = __ldcg(&g_pval[tid*BATCH + b]);
                bi   = __ldcg(&g_pidx[tid*BATCH + b]);
            }
            s_red[tid] = best; s_redi[tid] = bi;
            __syncthreads();
            if (tid == 0) {
                for (int u = 1; u < FCT; ++u)
                    if (s_red[u] > best) { best = s_red[u]; bi = s_redi[u]; }
                g_xtok[b] = (tfmask[t] > 0) ? target[t*BATCH + b] : bi;
            }
        }
        gridbar();
    }
}

extern "C" void kernel_launch(void* const* d_in, const int* in_sizes, int n_in,
                              void* d_out, int out_size)
{
    const float *ee,*de,*fw,*fb;
    const float *a1,*a2,*a3,*a4,*a5,*a6,*a7,*a8;
    const float *b1,*b2,*b3,*b4,*b5,*b6,*b7,*b8;
    const int *src,*tgt,*tfm;
    if (in_sizes[0] == SRCLEN*BATCH) {
        src=(const int*)d_in[0]; tgt=(const int*)d_in[1]; tfm=(const int*)d_in[2];
        ee=(const float*)d_in[3]; de=(const float*)d_in[4];
        a1=(const float*)d_in[5];  a2=(const float*)d_in[6];  a3=(const float*)d_in[7];  a4=(const float*)d_in[8];
        a5=(const float*)d_in[9];  a6=(const float*)d_in[10]; a7=(const float*)d_in[11]; a8=(const float*)d_in[12];
        b1=(const float*)d_in[13]; b2=(const float*)d_in[14]; b3=(const float*)d_in[15]; b4=(const float*)d_in[16];
        b5=(const float*)d_in[17]; b6=(const float*)d_in[18]; b7=(const float*)d_in[19]; b8=(const float*)d_in[20];
        fw=(const float*)d_in[21]; fb=(const float*)d_in[22];
    } else {
        ee=(const float*)d_in[0];
        a1=(const float*)d_in[1];  a2=(const float*)d_in[2];  a3=(const float*)d_in[3];  a4=(const float*)d_in[4];
        a5=(const float*)d_in[5];  a6=(const float*)d_in[6];  a7=(const float*)d_in[7];  a8=(const float*)d_in[8];
        de=(const float*)d_in[9];
        b1=(const float*)d_in[10]; b2=(const float*)d_in[11]; b3=(const float*)d_in[12]; b4=(const float*)d_in[13];
        b5=(const float*)d_in[14]; b6=(const float*)d_in[15]; b7=(const float*)d_in[16]; b8=(const float*)d_in[17];
        fw=(const float*)d_in[18]; fb=(const float*)d_in[19];
        src=(const int*)d_in[20]; tgt=(const int*)d_in[21]; tfm=(const int*)d_in[22];
    }
    float* out = (float*)d_out;
    cudaMemsetAsync(out, 0, (size_t)BATCH*VOCAB*sizeof(float));
    seq2seq_all<<<NBLK, NTHR>>>(ee, a1,a2,a3,a4, a5,a6,a7,a8,
                                de, b1,b2,b3,b4, b5,b6,b7,b8,
                                fw, fb, src, tgt, tfm, out);
}

// round 16
// speedup vs baseline: 1.0693x; 1.0693x over previous
#include <cuda_runtime.h>
#include <math.h>

#define BATCH  64
#define HID    512
#define EMBD   200
#define VOCAB  32000
#define SRCLEN 64
#define TGTLEN 64
#define NBLK   296
#define NTHR   256
#define SB     (BATCH*HID)
#define PARTSZ (BATCH*2048)
#define NSPL   8
#define FCT    500

typedef unsigned long long ull;

__device__ __forceinline__ ull pack2(float a, float b) {
    ull r; asm("mov.b64 %0, {%1,%2};" : "=l"(r) : "f"(a), "f"(b)); return r;
}
__device__ __forceinline__ ull ffma2(ull a, ull b, ull c) {
    ull d; asm("fma.rn.f32x2 %0, %1, %2, %3;" : "=l"(d) : "l"(a), "l"(b), "l"(c)); return d;
}
__device__ __forceinline__ float2 unpk(ull v) {
    float2 r; asm("mov.b64 {%0,%1}, %2;" : "=f"(r.x), "=f"(r.y) : "l"(v)); return r;
}

__device__ __align__(16) float g_parts0[NSPL*PARTSZ];
__device__ __align__(16) float g_parts1[NSPL*PARTSZ];
__device__ __align__(16) float g_h0[SB], g_c0[SB], g_h1[SB], g_c1[SB];
__device__ __align__(16) float g_bsum[4*2048];
__device__ int g_xtok[BATCH];
__device__ __align__(16) float g_pval[512*BATCH];
__device__ int g_pidx[512*BATCH];
__device__ unsigned g_barcnt;
__device__ volatile unsigned g_bargen;

__device__ __forceinline__ void gridbar() {
    __syncthreads();
    if (threadIdx.x == 0) {
        __threadfence();
        unsigned gen = g_bargen;
        if (atomicAdd(&g_barcnt, 1u) == NBLK - 1u) {
            g_barcnt = 0u;
            __threadfence();
            g_bargen = gen + 1u;
        } else {
            while (g_bargen == gen) __nanosleep(64);
            __threadfence();
        }
    }
    __syncthreads();
}

// 64x64 tile: acc[4b][2] += sum_k X[rows[b]][k]*W[c][k], k in [kbeg,kend)
// X staged in shared as duplicated f32x2 pairs -> no pack2 in the hot loop.
__device__ __forceinline__ void gemm_tile(
    const float* __restrict__ W, int ldW,
    const float* __restrict__ X, int ldX,
    const int* rows, int kbeg, int kend,
    float* Ws, ull* Xs, ull acc[4][2])
{
    int tid = threadIdx.x;
    int sj = tid >> 2, sk = (tid & 3) << 2;
    int rg = (tid >> 4) << 2, cg = (tid & 15) << 2;
    const float* Wp = W + (size_t)sj*ldW;
    const float* Xp = X + (size_t)rows[sj]*ldX;
    int nch = (kend - kbeg + 15) >> 4;
    float4 wv, xv;
    int kg = kbeg + sk;
    if (kg + 4 <= kend) { wv = *(const float4*)&Wp[kg]; xv = __ldcg((const float4*)&Xp[kg]); }
    else wv = xv = make_float4(0.f,0.f,0.f,0.f);
    {
        float* w_ = Ws + sk*68 + sj; ull* x_ = Xs + sk*66 + sj;
        w_[0]=wv.x; w_[68]=wv.y; w_[136]=wv.z; w_[204]=wv.w;
        x_[0]=pack2(xv.x,xv.x); x_[66]=pack2(xv.y,xv.y);
        x_[132]=pack2(xv.z,xv.z); x_[198]=pack2(xv.w,xv.w);
    }
    __syncthreads();
    if (nch > 1) {
        kg = kbeg + 16 + sk;
        if (kg + 4 <= kend) { wv = *(const float4*)&Wp[kg]; xv = __ldcg((const float4*)&Xp[kg]); }
        else wv = xv = make_float4(0.f,0.f,0.f,0.f);
    }
    for (int c = 0; c < nch; ++c) {
        int cb = c & 1;
        if (c + 1 < nch) {
            float* w_ = Ws + (cb^1)*1088 + sk*68 + sj;
            ull*   x_ = Xs + (cb^1)*1056 + sk*66 + sj;
            w_[0]=wv.x; w_[68]=wv.y; w_[136]=wv.z; w_[204]=wv.w;
            x_[0]=pack2(xv.x,xv.x); x_[66]=pack2(xv.y,xv.y);
            x_[132]=pack2(xv.z,xv.z); x_[198]=pack2(xv.w,xv.w);
        }
        if (c + 2 < nch) {
            kg = kbeg + (c+2)*16 + sk;
            if (kg + 4 <= kend) { wv = *(const float4*)&Wp[kg]; xv = __ldcg((const float4*)&Xp[kg]); }
            else wv = xv = make_float4(0.f,0.f,0.f,0.f);
        }
        const float* Wb = Ws + cb*1088;
        const ull*   Xb = Xs + cb*1056;
        #pragma unroll
        for (int q = 0; q < 16; ++q) {
            ulonglong2 xa = *(const ulonglong2*)&Xb[q*66 + rg];
            ulonglong2 xb = *(const ulonglong2*)&Xb[q*66 + rg + 2];
            ulonglong2 w2 = *(const ulonglong2*)&Wb[q*68 + cg];
            acc[0][0]=ffma2(xa.x,w2.x,acc[0][0]); acc[0][1]=ffma2(xa.x,w2.y,acc[0][1]);
            acc[1][0]=ffma2(xa.y,w2.x,acc[1][0]); acc[1][1]=ffma2(xa.y,w2.y,acc[1][1]);
            acc[2][0]=ffma2(xb.x,w2.x,acc[2][0]); acc[2][1]=ffma2(xb.x,w2.y,acc[2][1]);
            acc[3][0]=ffma2(xb.y,w2.x,acc[3][0]); acc[3][1]=ffma2(xb.y,w2.y,acc[3][1]);
        }
        __syncthreads();
    }
}

// K-split table: 8 splits per layer, bounds multiple of 4
__device__ __forceinline__ void split_range(int layer, int ks, int& isih, int& kbeg, int& kend) {
    if (layer == 0) {
        if (ks < 2) { isih = 1; kbeg = ks ? 112 : 0; kend = ks ? 200 : 112; }
        else {
            isih = 0;
            int h = ks - 2;   // 6 hh splits: 88,88,84,84,84,84
            kbeg = (h < 2) ? h*88 : 176 + (h-2)*84;
            kend = (h < 2) ? kbeg + 88 : kbeg + 84;
        }
    } else {
        isih = (ks < 4);
        kbeg = (ks & 3)*128; kend = kbeg + 128;
    }
}

// one gates job: job = ks*32 + ti (ti = 64-col tile of 2048)
__device__ __forceinline__ void gates_job(
    int job, int layer,
    const float* __restrict__ Wih, const float* __restrict__ Whh,
    const float* __restrict__ xsrc, const int* __restrict__ toks,
    const float* __restrict__ hprev, float* __restrict__ parts,
    float* Ws, ull* Xs, int* s_rows)
{
    int ks = job >> 5, ti = job & 31, tid = threadIdx.x;
    int isih, kbeg, kend;
    split_range(layer, ks, isih, kbeg, kend);
    const float *W, *X; int ldW, ldX, gather;
    if (isih) {
        ldW = (layer == 0) ? EMBD : HID;
        W = Wih; X = xsrc; ldX = ldW;
        gather = (layer == 0);
    } else {
        W = Whh; ldW = HID; X = hprev; ldX = HID; gather = 0;
    }
    __syncthreads();
    if (tid < 64) s_rows[tid] = gather ? __ldcg(&toks[tid]) : tid;
    __syncthreads();
    ull acc[4][2] = {{0,0},{0,0},{0,0},{0,0}};
    gemm_tile(W + (size_t)(ti*64)*ldW, ldW, X, ldX, s_rows, kbeg, kend, Ws, Xs, acc);
    int rg = tid >> 4, cg = tid & 15;
    #pragma unroll
    for (int r = 0; r < 4; ++r) {
        float2 a = unpk(acc[r][0]), b = unpk(acc[r][1]);
        *(float4*)&parts[(size_t)ks*PARTSZ + (size_t)(rg*4+r)*2048 + ti*64 + cg*4] =
            make_float4(a.x, a.y, b.x, b.y);
    }
}

__device__ __forceinline__ void epi_elem(int e, const float* __restrict__ bsum,
                                         const float* __restrict__ parts,
                                         float* __restrict__ h, float* __restrict__ c)
{
    int b = e >> 9, j = e & 511;
    float s[4];
    #pragma unroll
    for (int g = 0; g < 4; ++g) {
        int col = (g << 9) + j;
        float v = bsum[col];
        #pragma unroll
        for (int ks = 0; ks < NSPL; ++ks)
            v += __ldcg(&parts[(size_t)ks*PARTSZ + (size_t)b*2048 + col]);
        s[g] = v;
    }
    float iv = 1.f/(1.f+expf(-s[0])), fv = 1.f/(1.f+expf(-s[1]));
    float gv = tanhf(s[2]),           ov = 1.f/(1.f+expf(-s[3]));
    float cn = fv*__ldcg(&c[e]) + iv*gv;
    c[e] = cn;
    h[e] = ov*tanhf(cn);
}

__device__ __forceinline__ void fc_job(
    int vt, const float* __restrict__ fcW, const float* __restrict__ fcb,
    float* __restrict__ out, float* Ws, ull* Xs, int* s_rows,
    float* s_red, int* s_redi)
{
    int tid = threadIdx.x;
    __syncthreads();
    if (tid < 64) s_rows[tid] = tid;
    __syncthreads();
    ull acc[4][2] = {{0,0},{0,0},{0,0},{0,0}};
    gemm_tile(fcW + (size_t)(vt*64)*HID, HID, g_h1, HID, s_rows, 0, HID, Ws, Xs, acc);
    int rg = tid >> 4, cg = tid & 15, v0 = vt*64;
    float4 bv = *(const float4*)&fcb[v0 + cg*4];
    #pragma unroll
    for (int r = 0; r < 4; ++r) {
        int b = rg*4 + r;
        float2 a = unpk(acc[r][0]), d = unpk(acc[r][1]);
        float v_0 = a.x+bv.x, v_1 = a.y+bv.y, v_2 = d.x+bv.z, v_3 = d.y+bv.w;
        *(float4*)&out[(size_t)b*VOCAB + v0 + cg*4] = make_float4(v_0, v_1, v_2, v_3);
        float best = v_0; int bi = 0;
        if (v_1 > best) { best = v_1; bi = 1; }
        if (v_2 > best) { best = v_2; bi = 2; }
        if (v_3 > best) { best = v_3; bi = 3; }
        s_red[b*16 + cg] = best; s_redi[b*16 + cg] = v0 + cg*4 + bi;
    }
    __syncthreads();
    if (tid < 64) {
        float best = s_red[tid*16]; int bi = s_redi[tid*16];
        #pragma unroll
        for (int u = 1; u < 16; ++u) {
            float v = s_red[tid*16 + u];
            if (v > best) { best = v; bi = s_redi[tid*16 + u]; }
        }
        g_pval[vt*BATCH + tid] = best;
        g_pidx[vt*BATCH + tid] = bi;
    }
}

__global__ void __launch_bounds__(NTHR, 2) seq2seq_all(
    const float* __restrict__ enc_embed,
    const float* __restrict__ eWih0, const float* __restrict__ eWhh0,
    const float* __restrict__ ebih0, const float* __restrict__ ebhh0,
    const float* __restrict__ eWih1, const float* __restrict__ eWhh1,
    const float* __restrict__ ebih1, const float* __restrict__ ebhh1,
    const float* __restrict__ dec_embed,
    const float* __restrict__ dWih0, const float* __restrict__ dWhh0,
    const float* __restrict__ dbih0, const float* __restrict__ dbhh0,
    const float* __restrict__ dWih1, const float* __restrict__ dWhh1,
    const float* __restrict__ dbih1, const float* __restrict__ dbhh1,
    const float* __restrict__ fcW, const float* __restrict__ fcb,
    const int* __restrict__ src, const int* __restrict__ target,
    const int* __restrict__ tfmask, float* __restrict__ out)
{
    __shared__ __align__(16) float Ws[2*1088];
    __shared__ __align__(16) ull   Xs[2*1056];
    __shared__ int   s_rows[64];
    __shared__ float s_red[1024];
    __shared__ int   s_redi[1024];

    int bid = blockIdx.x, tid = threadIdx.x;
    int gtid = bid*NTHR + tid;
    const int GSTR = NBLK*NTHR;

    for (int e = gtid; e < SB; e += GSTR) { g_h0[e]=0.f; g_c0[e]=0.f; g_h1[e]=0.f; g_c1[e]=0.f; }
    for (int e = gtid; e < 2048; e += GSTR) {
        g_bsum[e]      = ebih0[e] + ebhh0[e];
        g_bsum[2048+e] = ebih1[e] + ebhh1[e];
        g_bsum[4096+e] = dbih0[e] + dbhh0[e];
        g_bsum[6144+e] = dbih1[e] + dbhh1[e];
    }
    if (gtid < BATCH) g_xtok[gtid] = target[gtid];
    gridbar();

    // ---- encoder ----
    for (int job = bid; job < 256; job += NBLK)
        gates_job(job, 0, eWih0, eWhh0, enc_embed, src, g_h0, g_parts0, Ws, Xs, s_rows);
    gridbar();
    for (int e = gtid; e < SB; e += GSTR) epi_elem(e, g_bsum, g_parts0, g_h0, g_c0);
    gridbar();
    for (int s = 0; s < SRCLEN-1; ++s) {
        for (int job = bid; job < 512; job += NBLK) {
            if (job < 256)
                gates_job(job, 1, eWih1, eWhh1, g_h0, (const int*)0, g_h1, g_parts1, Ws, Xs, s_rows);
            else
                gates_job(job-256, 0, eWih0, eWhh0, enc_embed, src + (s+1)*BATCH, g_h0, g_parts0, Ws, Xs, s_rows);
        }
        gridbar();
        for (int e = gtid; e < 2*SB; e += GSTR) {
            if (e < SB) epi_elem(e,    g_bsum+2048, g_parts1, g_h1, g_c1);
            else        epi_elem(e-SB, g_bsum,      g_parts0, g_h0, g_c0);
        }
        gridbar();
    }
    for (int job = bid; job < 256; job += NBLK)
        gates_job(job, 1, eWih1, eWhh1, g_h0, (const int*)0, g_h1, g_parts1, Ws, Xs, s_rows);
    gridbar();
    for (int e = gtid; e < SB; e += GSTR) epi_elem(e, g_bsum+2048, g_parts1, g_h1, g_c1);
    gridbar();

    // ---- decoder ----
    for (int t = 1; t < TGTLEN; ++t) {
        for (int job = bid; job < 256; job += NBLK)
            gates_job(job, 0, dWih0, dWhh0, dec_embed, g_xtok, g_h0, g_parts0, Ws, Xs, s_rows);
        gridbar();
        for (int e = gtid; e < SB; e += GSTR) epi_elem(e, g_bsum+4096, g_parts0, g_h0, g_c0);
        gridbar();
        for (int job = bid; job < 256; job += NBLK)
            gates_job(job, 1, dWih1, dWhh1, g_h0, (const int*)0, g_h1, g_parts1, Ws, Xs, s_rows);
        gridbar();
        for (int e = gtid; e < SB; e += GSTR) epi_elem(e, g_bsum+6144, g_parts1, g_h1, g_c1);
        gridbar();

        float* outT = out + (size_t)t*BATCH*VOCAB;
        for (int vt = bid; vt < FCT; vt += NBLK)
            fc_job(vt, fcW, fcb, outT, Ws, Xs, s_rows, s_red, s_redi);
        gridbar();

        if (bid < BATCH) {
            int b = bid;
            int q0 = tid*2;
            float best = -3.4e38f; int bi = 0;
            #pragma unroll
            for (int q = q0; q < q0+2; ++q) {
                if (q < FCT) {
                    float v = __ldcg(&g_pval[q*BATCH + b]);
                    if (v > best) { best = v; bi = __ldcg(&g_pidx[q*BATCH + b]); }
                }
            }
            s_red[tid] = best; s_redi[tid] = bi;
            __syncthreads();
            if (tid == 0) {
                for (int u = 1; u < 256; ++u)
                    if (s_red[u] > best) { best = s_red[u]; bi = s_redi[u]; }
                g_xtok[b] = (tfmask[t] > 0) ? target[t*BATCH + b] : bi;
            }
        }
        gridbar();
    }
}

extern "C" void kernel_launch(void* const* d_in, const int* in_sizes, int n_in,
                              void* d_out, int out_size)
{
    const float *ee,*de,*fw,*fb;
    const float *a1,*a2,*a3,*a4,*a5,*a6,*a7,*a8;
    const float *b1,*b2,*b3,*b4,*b5,*b6,*b7,*b8;
    const int *src,*tgt,*tfm;
    if (in_sizes[0] == SRCLEN*BATCH) {
        src=(const int*)d_in[0]; tgt=(const int*)d_in[1]; tfm=(const int*)d_in[2];
        ee=(const float*)d_in[3]; de=(const float*)d_in[4];
        a1=(const float*)d_in[5];  a2=(const float*)d_in[6];  a3=(const float*)d_in[7];  a4=(const float*)d_in[8];
        a5=(const float*)d_in[9];  a6=(const float*)d_in[10]; a7=(const float*)d_in[11]; a8=(const float*)d_in[12];
        b1=(const float*)d_in[13]; b2=(const float*)d_in[14]; b3=(const float*)d_in[15]; b4=(const float*)d_in[16];
        b5=(const float*)d_in[17]; b6=(const float*)d_in[18]; b7=(const float*)d_in[19]; b8=(const float*)d_in[20];
        fw=(const float*)d_in[21]; fb=(const float*)d_in[22];
    } else {
        ee=(const float*)d_in[0];
        a1=(const float*)d_in[1];  a2=(const float*)d_in[2];  a3=(const float*)d_in[3];  a4=(const float*)d_in[4];
        a5=(const float*)d_in[5];  a6=(const float*)d_in[6];  a7=(const float*)d_in[7];  a8=(const float*)d_in[8];
        de=(const float*)d_in[9];
        b1=(const float*)d_in[10]; b2=(const float*)d_in[11]; b3=(const float*)d_in[12]; b4=(const float*)d_in[13];
        b5=(const float*)d_in[14]; b6=(const float*)d_in[15]; b7=(const float*)d_in[16]; b8=(const float*)d_in[17];
        fw=(const float*)d_in[18]; fb=(const float*)d_in[19];
        src=(const int*)d_in[20]; tgt=(const int*)d_in[21]; tfm=(const int*)d_in[22];
    }
    float* out = (float*)d_out;
    cudaMemsetAsync(out, 0, (size_t)BATCH*VOCAB*sizeof(float));
    seq2seq_all<<<NBLK, NTHR>>>(ee, a1,a2,a3,a4, a5,a6,a7,a8,
                                de, b1,b2,b3,b4, b5,b6,b7,b8,
                                fw, fb, src, tgt, tfm, out);
}

// round 17
// speedup vs baseline: 1.2779x; 1.1951x over previous
#include <cuda_runtime.h>
#include <math.h>

#define BATCH  64
#define HID    512
#define EMBD   200
#define VOCAB  32000
#define SRCLEN 64
#define TGTLEN 64
#define NBLK   296
#define NTHR   256
#define SB     (BATCH*HID)
#define PARTSZ (BATCH*2048)
#define NSPL   8
#define FCT    250   /* 32000/128 */

typedef unsigned long long ull;

__device__ __forceinline__ ull pack2(float a, float b) {
    ull r; asm("mov.b64 %0, {%1,%2};" : "=l"(r) : "f"(a), "f"(b)); return r;
}
__device__ __forceinline__ ull ffma2(ull a, ull b, ull c) {
    ull d; asm("fma.rn.f32x2 %0, %1, %2, %3;" : "=l"(d) : "l"(a), "l"(b), "l"(c)); return d;
}
__device__ __forceinline__ float2 unpk(ull v) {
    float2 r; asm("mov.b64 {%0,%1}, %2;" : "=f"(r.x), "=f"(r.y) : "l"(v)); return r;
}

__device__ __align__(16) float g_parts0[NSPL*PARTSZ];
__device__ __align__(16) float g_parts1[NSPL*PARTSZ];
__device__ __align__(16) float g_h0[SB], g_c0[SB], g_h1[SB], g_c1[SB];
__device__ __align__(16) float g_bsum[4*2048];
__device__ int g_xtok[BATCH];
__device__ __align__(16) float g_pval[256*BATCH];
__device__ int g_pidx[256*BATCH];
__device__ unsigned g_barcnt;
__device__ volatile unsigned g_bargen;

__device__ __forceinline__ void gridbar() {
    __syncthreads();
    if (threadIdx.x == 0) {
        __threadfence();
        unsigned gen = g_bargen;
        if (atomicAdd(&g_barcnt, 1u) == NBLK - 1u) {
            g_barcnt = 0u;
            __threadfence();
            g_bargen = gen + 1u;
        } else {
            while (g_bargen == gen) __nanosleep(64);
            __threadfence();
        }
    }
    __syncthreads();
}

// ---- R14 gemm_tile (proven): 64x64, float staging, pack2 in loop ----
__device__ __forceinline__ void gemm_tile(
    const float* __restrict__ W, int ldW,
    const float* __restrict__ X, int ldX,
    const int* rows, int kbeg, int kend,
    float* Ws, float* Xs, ull acc[4][2])
{
    int tid = threadIdx.x;
    int sj = tid >> 2, sk = (tid & 3) << 2;
    int rg = tid >> 4, cg = tid & 15;
    const float* Wp = W + (size_t)sj*ldW;
    const float* Xp = X + (size_t)rows[sj]*ldX;
    int nch = (kend - kbeg + 15) >> 4;
    float4 wv, xv;
    int kg = kbeg + sk;
    if (kg + 4 <= kend) { wv = *(const float4*)&Wp[kg]; xv = __ldcg((const float4*)&Xp[kg]); }
    else wv = xv = make_float4(0.f,0.f,0.f,0.f);
    {
        float* w_ = Ws + sk*68 + sj; float* x_ = Xs + sk*68 + sj;
        w_[0]=wv.x; w_[68]=wv.y; w_[136]=wv.z; w_[204]=wv.w;
        x_[0]=xv.x; x_[68]=xv.y; x_[136]=xv.z; x_[204]=xv.w;
    }
    __syncthreads();
    if (nch > 1) {
        kg = kbeg + 16 + sk;
        if (kg + 4 <= kend) { wv = *(const float4*)&Wp[kg]; xv = __ldcg((const float4*)&Xp[kg]); }
        else wv = xv = make_float4(0.f,0.f,0.f,0.f);
    }
    for (int c = 0; c < nch; ++c) {
        int cb = c & 1;
        if (c + 1 < nch) {
            float* w_ = Ws + (cb^1)*1088 + sk*68 + sj;
            float* x_ = Xs + (cb^1)*1088 + sk*68 + sj;
            w_[0]=wv.x; w_[68]=wv.y; w_[136]=wv.z; w_[204]=wv.w;
            x_[0]=xv.x; x_[68]=xv.y; x_[136]=xv.z; x_[204]=xv.w;
        }
        if (c + 2 < nch) {
            kg = kbeg + (c+2)*16 + sk;
            if (kg + 4 <= kend) { wv = *(const float4*)&Wp[kg]; xv = __ldcg((const float4*)&Xp[kg]); }
            else wv = xv = make_float4(0.f,0.f,0.f,0.f);
        }
        const float* Wb = Ws + cb*1088;
        const float* Xb = Xs + cb*1088;
        #pragma unroll
        for (int q = 0; q < 16; ++q) {
            float4 x4 = *(const float4*)&Xb[q*68 + (rg<<2)];
            ulonglong2 w2 = *(const ulonglong2*)&Wb[q*68 + (cg<<2)];
            ull xr;
            xr = pack2(x4.x,x4.x); acc[0][0]=ffma2(xr,w2.x,acc[0][0]); acc[0][1]=ffma2(xr,w2.y,acc[0][1]);
            xr = pack2(x4.y,x4.y); acc[1][0]=ffma2(xr,w2.x,acc[1][0]); acc[1][1]=ffma2(xr,w2.y,acc[1][1]);
            xr = pack2(x4.z,x4.z); acc[2][0]=ffma2(xr,w2.x,acc[2][0]); acc[2][1]=ffma2(xr,w2.y,acc[2][1]);
            xr = pack2(x4.w,x4.w); acc[3][0]=ffma2(xr,w2.x,acc[3][0]); acc[3][1]=ffma2(xr,w2.y,acc[3][1]);
        }
        __syncthreads();
    }
}

__device__ __forceinline__ void split_range(int layer, int ks, int& isih, int& kbeg, int& kend) {
    if (layer == 0) {
        if (ks < 2) { isih = 1; kbeg = ks ? 112 : 0; kend = ks ? 200 : 112; }
        else {
            isih = 0;
            int h = ks - 2;
            kbeg = (h < 2) ? h*88 : 176 + (h-2)*84;
            kend = (h < 2) ? kbeg + 88 : kbeg + 84;
        }
    } else {
        isih = (ks < 4);
        kbeg = (ks & 3)*128; kend = kbeg + 128;
    }
}

__device__ __forceinline__ void gates_job(
    int job, int layer,
    const float* __restrict__ Wih, const float* __restrict__ Whh,
    const float* __restrict__ xsrc, const int* __restrict__ toks,
    const float* __restrict__ hprev, float* __restrict__ parts,
    float* Ws, float* Xs, int* s_rows)
{
    int ks = job >> 5, ti = job & 31, tid = threadIdx.x;
    int isih, kbeg, kend;
    split_range(layer, ks, isih, kbeg, kend);
    const float *W, *X; int ldW, ldX, gather;
    if (isih) {
        ldW = (layer == 0) ? EMBD : HID;
        W = Wih; X = xsrc; ldX = ldW;
        gather = (layer == 0);
    } else {
        W = Whh; ldW = HID; X = hprev; ldX = HID; gather = 0;
    }
    __syncthreads();
    if (tid < 64) s_rows[tid] = gather ? __ldcg(&toks[tid]) : tid;
    __syncthreads();
    ull acc[4][2] = {{0,0},{0,0},{0,0},{0,0}};
    gemm_tile(W + (size_t)(ti*64)*ldW, ldW, X, ldX, s_rows, kbeg, kend, Ws, Xs, acc);
    int rg = tid >> 4, cg = tid & 15;
    #pragma unroll
    for (int r = 0; r < 4; ++r) {
        float2 a = unpk(acc[r][0]), b = unpk(acc[r][1]);
        *(float4*)&parts[(size_t)ks*PARTSZ + (size_t)(rg*4+r)*2048 + ti*64 + cg*4] =
            make_float4(a.x, a.y, b.x, b.y);
    }
}

__device__ __forceinline__ void epi_elem(int e, const float* __restrict__ bsum,
                                         const float* __restrict__ parts,
                                         float* __restrict__ h, float* __restrict__ c)
{
    int b = e >> 9, j = e & 511;
    float s[4];
    #pragma unroll
    for (int g = 0; g < 4; ++g) {
        int col = (g << 9) + j;
        float v = bsum[col];
        #pragma unroll
        for (int ks = 0; ks < NSPL; ++ks)
            v += __ldcg(&parts[(size_t)ks*PARTSZ + (size_t)b*2048 + col]);
        s[g] = v;
    }
    float iv = 1.f/(1.f+expf(-s[0])), fv = 1.f/(1.f+expf(-s[1]));
    float gv = tanhf(s[2]),           ov = 1.f/(1.f+expf(-s[3]));
    float cn = fv*__ldcg(&c[e]) + iv*gv;
    c[e] = cn;
    h[e] = ov*tanhf(cn);
}

// deterministic warp argmax: max value, lowest global index on ties
__device__ __forceinline__ void warp_amax(float& v, int& i) {
    #pragma unroll
    for (int off = 16; off; off >>= 1) {
        float ov = __shfl_xor_sync(0xffffffffu, v, off);
        int   oi = __shfl_xor_sync(0xffffffffu, i, off);
        if (ov > v || (ov == v && oi < i)) { v = ov; i = oi; }
    }
}

// ---- FC: 128v x 64b tile. Warp = one 8-row group (X broadcast, pair-natural).
// Thread: 8 rows x 4 cols = acc[4 pairs][4 cols]. 16 FFMA2 per q, 4 pack2(w,w).
__device__ __forceinline__ void fc_job(
    int vt, const float* __restrict__ fcW, const float* __restrict__ fcb,
    float* __restrict__ out, float* Wf, float* Xf)
{
    int tid = threadIdx.x;
    int rg = tid >> 5;          // warp id -> rows 8rg..8rg+7
    int cg = tid & 31;          // cols cg*4..+3
    int wj = tid & 127, wk8 = (tid >> 7) << 3;   // W staging: col wj, k wk8..+7
    int xj = tid & 63,  xk4 = (tid >> 6) << 2;   // X staging: row xj, k xk4..+3
    const float* Wp = fcW + (size_t)(vt*128 + wj)*HID;
    const float* Xp = g_h1 + (size_t)xj*HID;
    const int NCH = HID/16;     // 32

    __syncthreads();
    ull acc[4][4] = {{0,0,0,0},{0,0,0,0},{0,0,0,0},{0,0,0,0}};

    float4 wa = *(const float4*)&Wp[wk8];
    float4 wb = *(const float4*)&Wp[wk8+4];
    float4 xv = __ldcg((const float4*)&Xp[xk4]);
    {
        float* w_ = Wf + wk8*132 + wj;
        w_[0]=wa.x; w_[132]=wa.y; w_[264]=wa.z; w_[396]=wa.w;
        w_[528]=wb.x; w_[660]=wb.y; w_[792]=wb.z; w_[924]=wb.w;
        float* x_ = Xf + xk4*72 + xj;
        x_[0]=xv.x; x_[72]=xv.y; x_[144]=xv.z; x_[216]=xv.w;
    }
    __syncthreads();
    wa = *(const float4*)&Wp[16+wk8];
    wb = *(const float4*)&Wp[16+wk8+4];
    xv = __ldcg((const float4*)&Xp[16+xk4]);

    for (int c = 0; c < NCH; ++c) {
        int cb = c & 1;
        if (c + 1 < NCH) {
            float* w_ = Wf + (cb^1)*2112 + wk8*132 + wj;
            w_[0]=wa.x; w_[132]=wa.y; w_[264]=wa.z; w_[396]=wa.w;
            w_[528]=wb.x; w_[660]=wb.y; w_[792]=wb.z; w_[924]=wb.w;
            float* x_ = Xf + (cb^1)*1152 + xk4*72 + xj;
            x_[0]=xv.x; x_[72]=xv.y; x_[144]=xv.z; x_[216]=xv.w;
        }
        if (c + 2 < NCH) {
            int k0 = (c+2)*16;
            wa = *(const float4*)&Wp[k0+wk8];
            wb = *(const float4*)&Wp[k0+wk8+4];
            xv = __ldcg((const float4*)&Xp[k0+xk4]);
        }
        const float* Wb_ = Wf + cb*2112;
        const ull*   Xb_ = (const ull*)(Xf + cb*1152);
        #pragma unroll
        for (int q = 0; q < 16; ++q) {
            ulonglong2 xpA = *(const ulonglong2*)&Xb_[q*36 + (rg<<2)];      // pairs 0,1
            ulonglong2 xpB = *(const ulonglong2*)&Xb_[q*36 + (rg<<2) + 2];  // pairs 2,3
            float4 w4 = *(const float4*)&Wb_[q*132 + (cg<<2)];
            ull wd;
            wd = pack2(w4.x,w4.x);
            acc[0][0]=ffma2(xpA.x,wd,acc[0][0]); acc[1][0]=ffma2(xpA.y,wd,acc[1][0]);
            acc[2][0]=ffma2(xpB.x,wd,acc[2][0]); acc[3][0]=ffma2(xpB.y,wd,acc[3][0]);
            wd = pack2(w4.y,w4.y);
            acc[0][1]=ffma2(xpA.x,wd,acc[0][1]); acc[1][1]=ffma2(xpA.y,wd,acc[1][1]);
            acc[2][1]=ffma2(xpB.x,wd,acc[2][1]); acc[3][1]=ffma2(xpB.y,wd,acc[3][1]);
            wd = pack2(w4.z,w4.z);
            acc[0][2]=ffma2(xpA.x,wd,acc[0][2]); acc[1][2]=ffma2(xpA.y,wd,acc[1][2]);
            acc[2][2]=ffma2(xpB.x,wd,acc[2][2]); acc[3][2]=ffma2(xpB.y,wd,acc[3][2]);
            wd = pack2(w4.w,w4.w);
            acc[0][3]=ffma2(xpA.x,wd,acc[0][3]); acc[1][3]=ffma2(xpA.y,wd,acc[1][3]);
            acc[2][3]=ffma2(xpB.x,wd,acc[2][3]); acc[3][3]=ffma2(xpB.y,wd,acc[3][3]);
        }
        __syncthreads();
    }

    int v0 = vt*128 + (cg<<2);
    float4 bv = *(const float4*)&fcb[v0];
    #pragma unroll
    for (int p = 0; p < 4; ++p) {
        int b0 = (rg<<3) + (p<<1), b1 = b0 + 1;
        float2 t0 = unpk(acc[p][0]), t1 = unpk(acc[p][1]);
        float2 t2 = unpk(acc[p][2]), t3 = unpk(acc[p][3]);
        float r0[4] = {t0.x+bv.x, t1.x+bv.y, t2.x+bv.z, t3.x+bv.w};
        float r1[4] = {t0.y+bv.x, t1.y+bv.y, t2.y+bv.z, t3.y+bv.w};
        *(float4*)&out[(size_t)b0*VOCAB + v0] = make_float4(r0[0],r0[1],r0[2],r0[3]);
        *(float4*)&out[(size_t)b1*VOCAB + v0] = make_float4(r1[0],r1[1],r1[2],r1[3]);
        float bv0 = r0[0]; int bi0 = v0;
        float bv1 = r1[0]; int bi1 = v0;
        #pragma unroll
        for (int u = 1; u < 4; ++u) {
            if (r0[u] > bv0) { bv0 = r0[u]; bi0 = v0 + u; }
            if (r1[u] > bv1) { bv1 = r1[u]; bi1 = v0 + u; }
        }
        warp_amax(bv0, bi0);
        warp_amax(bv1, bi1);
        if ((tid & 31) == 0) {
            g_pval[vt*BATCH + b0] = bv0; g_pidx[vt*BATCH + b0] = bi0;
            g_pval[vt*BATCH + b1] = bv1; g_pidx[vt*BATCH + b1] = bi1;
        }
    }
}

__global__ void __launch_bounds__(NTHR, 2) seq2seq_all(
    const float* __restrict__ enc_embed,
    const float* __restrict__ eWih0, const float* __restrict__ eWhh0,
    const float* __restrict__ ebih0, const float* __restrict__ ebhh0,
    const float* __restrict__ eWih1, const float* __restrict__ eWhh1,
    const float* __restrict__ ebih1, const float* __restrict__ ebhh1,
    const float* __restrict__ dec_embed,
    const float* __restrict__ dWih0, const float* __restrict__ dWhh0,
    const float* __restrict__ dbih0, const float* __restrict__ dbhh0,
    const float* __restrict__ dWih1, const float* __restrict__ dWhh1,
    const float* __restrict__ dbih1, const float* __restrict__ dbhh1,
    const float* __restrict__ fcW, const float* __restrict__ fcb,
    const int* __restrict__ src, const int* __restrict__ target,
    const int* __restrict__ tfmask, float* __restrict__ out)
{
    // union buffer: gates Ws=buf[0:2176), Xs=buf[2176:4352); FC Wf=buf[0:4224), Xf=buf[4224:6528)
    __shared__ __align__(16) float s_buf[6528];
    __shared__ int   s_rows[64];
    __shared__ float s_red[256];
    __shared__ int   s_redi[256];

    float* gWs = s_buf;
    float* gXs = s_buf + 2176;
    float* fWf = s_buf;
    float* fXf = s_buf + 4224;

    int bid = blockIdx.x, tid = threadIdx.x;
    int gtid = bid*NTHR + tid;
    const int GSTR = NBLK*NTHR;

    for (int e = gtid; e < SB; e += GSTR) { g_h0[e]=0.f; g_c0[e]=0.f; g_h1[e]=0.f; g_c1[e]=0.f; }
    for (int e = gtid; e < 2048; e += GSTR) {
        g_bsum[e]      = ebih0[e] + ebhh0[e];
        g_bsum[2048+e] = ebih1[e] + ebhh1[e];
        g_bsum[4096+e] = dbih0[e] + dbhh0[e];
        g_bsum[6144+e] = dbih1[e] + dbhh1[e];
    }
    if (gtid < BATCH) g_xtok[gtid] = target[gtid];
    gridbar();

    // ---- encoder ----
    for (int job = bid; job < 256; job += NBLK)
        gates_job(job, 0, eWih0, eWhh0, enc_embed, src, g_h0, g_parts0, gWs, gXs, s_rows);
    gridbar();
    for (int e = gtid; e < SB; e += GSTR) epi_elem(e, g_bsum, g_parts0, g_h0, g_c0);
    gridbar();
    for (int s = 0; s < SRCLEN-1; ++s) {
        for (int job = bid; job < 512; job += NBLK) {
            if (job < 256)
                gates_job(job, 1, eWih1, eWhh1, g_h0, (const int*)0, g_h1, g_parts1, gWs, gXs, s_rows);
            else
                gates_job(job-256, 0, eWih0, eWhh0, enc_embed, src + (s+1)*BATCH, g_h0, g_parts0, gWs, gXs, s_rows);
        }
        gridbar();
        for (int e = gtid; e < 2*SB; e += GSTR) {
            if (e < SB) epi_elem(e,    g_bsum+2048, g_parts1, g_h1, g_c1);
            else        epi_elem(e-SB, g_bsum,      g_parts0, g_h0, g_c0);
        }
        gridbar();
    }
    for (int job = bid; job < 256; job += NBLK)
        gates_job(job, 1, eWih1, eWhh1, g_h0, (const int*)0, g_h1, g_parts1, gWs, gXs, s_rows);
    gridbar();
    for (int e = gtid; e < SB; e += GSTR) epi_elem(e, g_bsum+2048, g_parts1, g_h1, g_c1);
    gridbar();

    // ---- decoder ----
    for (int t = 1; t < TGTLEN; ++t) {
        for (int job = bid; job < 256; job += NBLK)
            gates_job(job, 0, dWih0, dWhh0, dec_embed, g_xtok, g_h0, g_parts0, gWs, gXs, s_rows);
        gridbar();
        for (int e = gtid; e < SB; e += GSTR) epi_elem(e, g_bsum+4096, g_parts0, g_h0, g_c0);
        gridbar();
        for (int job = bid; job < 256; job += NBLK)
            gates_job(job, 1, dWih1, dWhh1, g_h0, (const int*)0, g_h1, g_parts1, gWs, gXs, s_rows);
        gridbar();
        for (int e = gtid; e < SB; e += GSTR) epi_elem(e, g_bsum+6144, g_parts1, g_h1, g_c1);
        gridbar();

        float* outT = out + (size_t)t*BATCH*VOCAB;
        for (int vt = bid; vt < FCT; vt += NBLK)
            fc_job(vt, fcW, fcb, outT, fWf, fXf);
        gridbar();

        if (bid < BATCH) {
            int b = bid;
            float best = -3.4e38f; int bi = 0;
            if (tid < FCT) {
                best = __ldcg(&g_pval[tid*BATCH + b]);
                bi   = __ldcg(&g_pidx[tid*BATCH + b]);
            }
            s_red[tid] = best; s_redi[tid] = bi;
            __syncthreads();
            if (tid == 0) {
                for (int u = 1; u < FCT; ++u)
                    if (s_red[u] > best) { best = s_red[u]; bi = s_redi[u]; }
                g_xtok[b] = (tfmask[t] > 0) ? target[t*BATCH + b] : bi;
            }
        }
        gridbar();
    }
}

extern "C" void kernel_launch(void* const* d_in, const int* in_sizes, int n_in,
                              void* d_out, int out_size)
{
    const float *ee,*de,*fw,*fb;
    const float *a1,*a2,*a3,*a4,*a5,*a6,*a7,*a8;
    const float *b1,*b2,*b3,*b4,*b5,*b6,*b7,*b8;
    const int *src,*tgt,*tfm;
    if (in_sizes[0] == SRCLEN*BATCH) {
        src=(const int*)d_in[0]; tgt=(const int*)d_in[1]; tfm=(const int*)d_in[2];
        ee=(const float*)d_in[3]; de=(const float*)d_in[4];
        a1=(const float*)d_in[5];  a2=(const float*)d_in[6];  a3=(const float*)d_in[7];  a4=(const float*)d_in[8];
        a5=(const float*)d_in[9];  a6=(const float*)d_in[10]; a7=(const float*)d_in[11]; a8=(const float*)d_in[12];
        b1=(const float*)d_in[13]; b2=(const float*)d_in[14]; b3=(const float*)d_in[15]; b4=(const float*)d_in[16];
        b5=(const float*)d_in[17]; b6=(const float*)d_in[18]; b7=(const float*)d_in[19]; b8=(const float*)d_in[20];
        fw=(const float*)d_in[21]; fb=(const float*)d_in[22];
    } else {
        ee=(const float*)d_in[0];
        a1=(const float*)d_in[1];  a2=(const float*)d_in[2];  a3=(const float*)d_in[3];  a4=(const float*)d_in[4];
        a5=(const float*)d_in[5];  a6=(const float*)d_in[6];  a7=(const float*)d_in[7];  a8=(const float*)d_in[8];
        de=(const float*)d_in[9];
        b1=(const float*)d_in[10]; b2=(const float*)d_in[11]; b3=(const float*)d_in[12]; b4=(const float*)d_in[13];
        b5=(const float*)d_in[14]; b6=(const float*)d_in[15]; b7=(const float*)d_in[16]; b8=(const float*)d_in[17];
        fw=(const float*)d_in[18]; fb=(const float*)d_in[19];
        src=(const int*)d_in[20]; tgt=(const int*)d_in[21]; tfm=(const int*)d_in[22];
    }
    float* out = (float*)d_out;
    cudaMemsetAsync(out, 0, (size_t)BATCH*VOCAB*sizeof(float));
    seq2seq_all<<<NBLK, NTHR>>>(ee, a1,a2,a3,a4, a5,a6,a7,a8,
                                de, b1,b2,b3,b4, b5,b6,b7,b8,
                                fw, fb, src, tgt, tfm, out);
}